// round 6
// baseline (speedup 1.0000x reference)
#include <cuda_runtime.h>

// SSIM loss, fused separable 11x11 Gaussian, B=16 C=3 H=512 W=512 fp32.
// v6: occupancy/balance restructure.
//   grid = (6 row-chunks, 48 planes) = 288 blocks -> one balanced wave at
//   2 CTAs/SM. 256 threads/CTA, 2 cols/thread (one f32x2 pack) -> small
//   register ring, ~16 warps/SM for latency hiding.
// Vertical conv: register ring of 11 packed raw rows, f32x2 math with packed
// weight regs. Fields: mu1, mu2, conv(a^2+b^2), conv(ab).
// Horizontal conv: scalar FFMA-imm; own 2 cols from registers, halos via
// 6 aligned LDS.64 per field from double-buffered padded smem.
// Finalization folded into the last block (atomicInc wrap, replay-safe).

#define HH 512
#define WW 512
#define NTHREADS 256
#define NPIX 12582912.0
#define GX 6
#define GY 48
#define NBLOCKS (GX * GY)

typedef unsigned long long u64;

__device__ constexpr float KW[11] = {
    0.00102839f, 0.00759876f, 0.03600077f, 0.10936069f, 0.21300554f,
    0.26601172f,
    0.21300554f, 0.10936069f, 0.03600077f, 0.00759876f, 0.00102839f};

__device__ double g_partial[NBLOCKS];
__device__ unsigned g_count = 0;

// ---- f32x2 packed helpers (sm_100+ PTX) ----
__device__ __forceinline__ u64 pk2(float lo, float hi) {
    u64 r; asm("mov.b64 %0, {%1, %2};" : "=l"(r) : "f"(lo), "f"(hi)); return r;
}
__device__ __forceinline__ void upk2(u64 v, float& lo, float& hi) {
    asm("mov.b64 {%0, %1}, %2;" : "=f"(lo), "=f"(hi) : "l"(v));
}
__device__ __forceinline__ u64 f2add(u64 a, u64 b) {
    u64 r; asm("add.rn.f32x2 %0, %1, %2;" : "=l"(r) : "l"(a), "l"(b)); return r;
}
__device__ __forceinline__ u64 f2mul(u64 a, u64 b) {
    u64 r; asm("mul.rn.f32x2 %0, %1, %2;" : "=l"(r) : "l"(a), "l"(b)); return r;
}
__device__ __forceinline__ u64 f2fma(u64 a, u64 b, u64 c) {
    u64 r; asm("fma.rn.f32x2 %0, %1, %2, %3;" : "=l"(r) : "l"(a), "l"(b), "l"(c));
    return r;
}

__device__ __forceinline__ u64 load_row_pk(const float* __restrict__ p,
                                           int row, int c0) {
    if ((unsigned)row < (unsigned)HH)
        return *reinterpret_cast<const u64*>(p + row * WW + c0);
    return 0ull;
}

__global__ __launch_bounds__(NTHREADS, 2)
void ssim_kernel(const float* __restrict__ sr, const float* __restrict__ hr,
                 float* __restrict__ out) {
    const int plane = blockIdx.y;
    const int bx = blockIdx.x;
    const int r0 = 85 * bx + min(bx, 2);          // chunks: 86,86,85,85,85,85
    const int nr = 86 - (bx >= 2);
    const int tid = threadIdx.x;
    const int c0 = tid * 2;                       // this thread's 2 columns

    const float* __restrict__ pa = sr + (size_t)plane * HH * WW;
    const float* __restrict__ pb = hr + (size_t)plane * HH * WW;

    // Double-buffered line buffer: 4 fields, data col c at word c+8,
    // halo zeros at words [0..7] and [520..527].
    __shared__ __align__(16) float vsbuf[2][4][528];

    if (tid < 128) {
        int b = tid >> 6;
        int f = (tid >> 4) & 3;
        int k = tid & 15;
        int idx = (k < 8) ? k : (512 + k);
        vsbuf[b][f][idx] = 0.f;
    }
    __syncthreads();

    // Packed weight constants (symmetric kernel -> 6 uniques).
    u64 WKP[6];
#pragma unroll
    for (int k = 0; k < 6; ++k) WKP[k] = pk2(KW[k], KW[k]);

    // Register ring of packed raw rows (last 11 loaded rows).
    u64 ra[11], rb[11], na, nb;
#pragma unroll
    for (int k = 0; k < 10; ++k) {
        ra[k + 1] = load_row_pk(pa, r0 - 5 + k, c0);
        rb[k + 1] = load_row_pk(pb, r0 - 5 + k, c0);
    }
    na = load_row_pk(pa, r0 + 5, c0);
    nb = load_row_pk(pb, r0 + 5, c0);

    const u64 TWO  = pk2(2.f, 2.f);
    const u64 NEG1 = pk2(-1.f, -1.f);
    const u64 C1   = pk2(1e-4f, 1e-4f);
    const u64 C2   = pk2(9e-4f, 9e-4f);

    float acc = 0.f;

#pragma unroll 4
    for (int i = 0; i < nr; ++i) {
        const int buf = i & 1;

        // shift ring, consume prefetch, prefetch next row
#pragma unroll
        for (int k = 0; k < 10; ++k) { ra[k] = ra[k + 1]; rb[k] = rb[k + 1]; }
        ra[10] = na; rb[10] = nb;
        na = load_row_pk(pa, r0 + 6 + i, c0);
        nb = load_row_pk(pb, r0 + 6 + i, c0);

        // vertical 11-tap conv, packed; center tap initializes.
        u64 s0, s1, sqa, sqb, srr;
        {
            u64 a = ra[5], b = rb[5];
            u64 wa = f2mul(WKP[5], a);
            u64 wb = f2mul(WKP[5], b);
            s0 = wa; s1 = wb;
            sqa = f2mul(wa, a);
            sqb = f2mul(wb, b);
            srr = f2mul(wa, b);
        }
#pragma unroll
        for (int k = 0; k < 11; ++k) {
            if (k == 5) continue;
            const int wi = (k < 5) ? k : (10 - k);
            u64 a = ra[k], b = rb[k];
            u64 wa = f2mul(WKP[wi], a);
            u64 wb = f2mul(WKP[wi], b);
            s0  = f2add(s0, wa);
            s1  = f2add(s1, wb);
            sqa = f2fma(wa, a, sqa);
            sqb = f2fma(wb, b, sqb);
            srr = f2fma(wa, b, srr);
        }
        u64 qq = f2add(sqa, sqb);

        // publish vertical sums (one STS.64 per field, 8B aligned)
        *reinterpret_cast<u64*>(&vsbuf[buf][0][8 + c0]) = s0;
        *reinterpret_cast<u64*>(&vsbuf[buf][1][8 + c0]) = s1;
        *reinterpret_cast<u64*>(&vsbuf[buf][2][8 + c0]) = qq;
        *reinterpret_cast<u64*>(&vsbuf[buf][3][8 + c0]) = srr;
        __syncthreads();

        // horizontal 11-tap conv, scalar FFMA-imm.
        // window for outputs (c0, c0+1): cols c0-5 .. c0+6 -> v[m+6], m=-6..7.
        // own cols (m=0,1) from registers; halos via 6 aligned LDS.64.
        float cv[4][2];
        u64 own[4] = {s0, s1, qq, srr};
#pragma unroll
        for (int f = 0; f < 4; ++f) {
            const float* wf = &vsbuf[buf][f][0];
            float v[14];
            float2 L0 = *reinterpret_cast<const float2*>(&wf[c0 + 2]);
            float2 L1 = *reinterpret_cast<const float2*>(&wf[c0 + 4]);
            float2 L2 = *reinterpret_cast<const float2*>(&wf[c0 + 6]);
            float2 R0 = *reinterpret_cast<const float2*>(&wf[c0 + 10]);
            float2 R1 = *reinterpret_cast<const float2*>(&wf[c0 + 12]);
            float2 R2 = *reinterpret_cast<const float2*>(&wf[c0 + 14]);
            v[0] = L0.x; v[1] = L0.y;
            v[2] = L1.x; v[3] = L1.y;
            v[4] = L2.x; v[5] = L2.y;
            upk2(own[f], v[6], v[7]);
            v[8] = R0.x; v[9] = R0.y;
            v[10] = R1.x; v[11] = R1.y;
            v[12] = R2.x; v[13] = R2.y;
#pragma unroll
            for (int j = 0; j < 2; ++j) {
                float s = KW[5] * v[6 + j];
#pragma unroll
                for (int k = 0; k < 11; ++k) {
                    if (k == 5) continue;
                    s += KW[k] * v[1 + j + k];
                }
                cv[f][j] = s;
            }
        }

        // SSIM map, packed (2 cols in one pack)
        {
            u64 m1 = pk2(cv[0][0], cv[0][1]);
            u64 m2 = pk2(cv[1][0], cv[1][1]);
            u64 q2 = pk2(cv[2][0], cv[2][1]);
            u64 rr = pk2(cv[3][0], cv[3][1]);

            u64 m12 = f2mul(m1, m2);
            u64 sms = f2fma(m2, m2, f2mul(m1, m1));      // m1^2 + m2^2
            u64 num1 = f2fma(TWO, m12, C1);              // 2*m12 + c1
            u64 sig12 = f2fma(m12, NEG1, rr);            // r - m12
            u64 num2 = f2fma(TWO, sig12, C2);            // 2*sig12 + c2
            u64 den1 = f2add(sms, C1);
            u64 den2 = f2add(f2fma(sms, NEG1, q2), C2);  // q - sms + c2
            u64 num = f2mul(num1, num2);
            u64 den = f2mul(den1, den2);

            float n0, n1, d0, d1;
            upk2(num, n0, n1);
            upk2(den, d0, d1);
            acc += __fdividef(n0, d0);
            acc += __fdividef(n1, d1);
        }
        __syncthreads();  // vsbuf[buf] consumed before overwrite in 2 iters
    }

    // block reduction -> per-block partial
#pragma unroll
    for (int o = 16; o > 0; o >>= 1)
        acc += __shfl_down_sync(0xFFFFFFFFu, acc, o);

    __shared__ float wsum[8];
    __shared__ int is_last;
    if ((tid & 31) == 0) wsum[tid >> 5] = acc;
    __syncthreads();
    if (tid == 0) {
        double s = 0.0;
#pragma unroll
        for (int w = 0; w < 8; ++w) s += (double)wsum[w];
        g_partial[blockIdx.y * GX + blockIdx.x] = s;
        __threadfence();
        unsigned old = atomicInc(&g_count, NBLOCKS - 1);  // wraps to 0
        is_last = (old == NBLOCKS - 1);
    }
    __syncthreads();

    // last block finalizes (replay-deterministic: counter wraps to 0)
    if (is_last) {
        __threadfence();
        double s = 0.0;
        for (int i = tid; i < NBLOCKS; i += NTHREADS) s += __ldcg(&g_partial[i]);
#pragma unroll
        for (int o = 16; o > 0; o >>= 1)
            s += __shfl_down_sync(0xFFFFFFFFu, s, o);
        __shared__ double dsm[8];
        if ((tid & 31) == 0) dsm[tid >> 5] = s;
        __syncthreads();
        if (tid == 0) {
            double tot = 0.0;
#pragma unroll
            for (int w = 0; w < 8; ++w) tot += dsm[w];
            out[0] = (float)(1.0 - tot / NPIX);
        }
    }
}

extern "C" void kernel_launch(void* const* d_in, const int* in_sizes, int n_in,
                              void* d_out, int out_size) {
    const float* sr = (const float*)d_in[0];
    const float* hr = (const float*)d_in[1];
    float* out = (float*)d_out;

    dim3 grid(GX, GY);
    ssim_kernel<<<grid, NTHREADS>>>(sr, hr, out);
}

// round 7
// speedup vs baseline: 1.0979x; 1.0979x over previous
#include <cuda_runtime.h>

// SSIM loss, fused separable 11x11 Gaussian, B=16 C=3 H=512 W=512 fp32.
// v7: barrier-cadence + balance restructure over the R5 shape.
//   grid = (9 row-chunks, 48 planes) = 432 blocks = 144 SM x 3 CTAs balanced.
//   128 threads, 4 cols/thread (2 f32x2 packs).
//   TWO rows per iteration into a quad-buffered smem line buffer ->
//   ONE __syncthreads per 2 rows (4x fewer barriers than v5).
// Vertical conv: register ring of packed raw rows, packed-weight f32x2 math.
// Fields: mu1, mu2, conv(a^2+b^2), conv(ab).
// Horizontal conv: scalar FFMA-imm from padded smem (row B uses own-col regs).
// Finalization folded into the last block (atomicInc wrap, replay-safe).

#define HH 512
#define WW 512
#define NTHREADS 128
#define NPIX 12582912.0
#define GX 9
#define GY 48
#define NBLOCKS (GX * GY)

typedef unsigned long long u64;

__device__ constexpr float KW[11] = {
    0.00102839f, 0.00759876f, 0.03600077f, 0.10936069f, 0.21300554f,
    0.26601172f,
    0.21300554f, 0.10936069f, 0.03600077f, 0.00759876f, 0.00102839f};

__device__ double g_partial[NBLOCKS];
__device__ unsigned g_count = 0;

// ---- f32x2 packed helpers (sm_100+ PTX) ----
__device__ __forceinline__ u64 pk2(float lo, float hi) {
    u64 r; asm("mov.b64 %0, {%1, %2};" : "=l"(r) : "f"(lo), "f"(hi)); return r;
}
__device__ __forceinline__ void upk2(u64 v, float& lo, float& hi) {
    asm("mov.b64 {%0, %1}, %2;" : "=f"(lo), "=f"(hi) : "l"(v));
}
__device__ __forceinline__ u64 f2add(u64 a, u64 b) {
    u64 r; asm("add.rn.f32x2 %0, %1, %2;" : "=l"(r) : "l"(a), "l"(b)); return r;
}
__device__ __forceinline__ u64 f2mul(u64 a, u64 b) {
    u64 r; asm("mul.rn.f32x2 %0, %1, %2;" : "=l"(r) : "l"(a), "l"(b)); return r;
}
__device__ __forceinline__ u64 f2fma(u64 a, u64 b, u64 c) {
    u64 r; asm("fma.rn.f32x2 %0, %1, %2, %3;" : "=l"(r) : "l"(a), "l"(b), "l"(c));
    return r;
}

__device__ __forceinline__ void load_row_pk(const float* __restrict__ p,
                                            int row, int c0, u64 o[2]) {
    if ((unsigned)row < (unsigned)HH) {
        ulonglong2 v = *reinterpret_cast<const ulonglong2*>(p + row * WW + c0);
        o[0] = v.x;
        o[1] = v.y;
    } else {
        o[0] = 0ull; o[1] = 0ull;
    }
}

__global__ __launch_bounds__(NTHREADS, 3)
void ssim_kernel(const float* __restrict__ sr, const float* __restrict__ hr,
                 float* __restrict__ out) {
    const int plane = blockIdx.y;
    const int bx = blockIdx.x;
    // chunks: 58,58,58,58,56,56,56,56,56 (all even; sum = 512)
    const int r0 = (bx < 4) ? 58 * bx : (232 + 56 * (bx - 4));
    const int npairs = (bx < 4) ? 29 : 28;
    const int tid = threadIdx.x;
    const int c0 = tid * 4;

    const float* __restrict__ pa = sr + (size_t)plane * HH * WW;
    const float* __restrict__ pb = hr + (size_t)plane * HH * WW;

    // Quad-buffered line buffer: 4 bufs x 4 fields, data col c at word c+8,
    // halo zeros at words [0..7] and [520..527].
    __shared__ __align__(16) float vsbuf[4][4][528];

    {
        // 4 bufs * 4 fields * 16 halo words = 256 inits, 2 per thread
        for (int q = tid; q < 256; q += NTHREADS) {
            int b = q >> 6;
            int f = (q >> 4) & 3;
            int k = q & 15;
            int idx = (k < 8) ? k : (512 + k);
            vsbuf[b][f][idx] = 0.f;
        }
    }
    __syncthreads();

    // Packed weight constants (symmetric kernel -> 6 uniques).
    u64 WKP[6];
#pragma unroll
    for (int k = 0; k < 6; ++k) WKP[k] = pk2(KW[k], KW[k]);

    // Register ring of packed raw rows (last 11 loaded rows).
    u64 ra[11][2], rb[11][2], na[2], nb[2];
#pragma unroll
    for (int k = 0; k < 10; ++k) {
        load_row_pk(pa, r0 - 5 + k, c0, ra[k + 1]);
        load_row_pk(pb, r0 - 5 + k, c0, rb[k + 1]);
    }
    load_row_pk(pa, r0 + 5, c0, na);
    load_row_pk(pb, r0 + 5, c0, nb);

    const u64 TWO  = pk2(2.f, 2.f);
    const u64 NEG1 = pk2(-1.f, -1.f);
    const u64 C1   = pk2(1e-4f, 1e-4f);
    const u64 C2   = pk2(9e-4f, 9e-4f);

    float acc = 0.f;

#pragma unroll 2
    for (int p = 0; p < npairs; ++p) {
        const int bufA = (p & 1) * 2;
        const int bufB = bufA + 1;
        const int i = 2 * p;  // row A index within chunk

        // ---------- Row A: vertical conv -> smem (sums released) ----------
#pragma unroll
        for (int k = 0; k < 10; ++k) {
#pragma unroll
            for (int q = 0; q < 2; ++q) { ra[k][q] = ra[k + 1][q]; rb[k][q] = rb[k + 1][q]; }
        }
#pragma unroll
        for (int q = 0; q < 2; ++q) { ra[10][q] = na[q]; rb[10][q] = nb[q]; }
        load_row_pk(pa, r0 + 6 + i, c0, na);
        load_row_pk(pb, r0 + 6 + i, c0, nb);

        {
            u64 s0[2], s1[2], sqa[2], sqb[2], srr[2];
#pragma unroll
            for (int q = 0; q < 2; ++q) {
                u64 a = ra[5][q], b = rb[5][q];
                u64 wa = f2mul(WKP[5], a);
                u64 wb = f2mul(WKP[5], b);
                s0[q] = wa; s1[q] = wb;
                sqa[q] = f2mul(wa, a);
                sqb[q] = f2mul(wb, b);
                srr[q] = f2mul(wa, b);
            }
#pragma unroll
            for (int k = 0; k < 11; ++k) {
                if (k == 5) continue;
                const int wi = (k < 5) ? k : (10 - k);
#pragma unroll
                for (int q = 0; q < 2; ++q) {
                    u64 a = ra[k][q], b = rb[k][q];
                    u64 wa = f2mul(WKP[wi], a);
                    u64 wb = f2mul(WKP[wi], b);
                    s0[q]  = f2add(s0[q], wa);
                    s1[q]  = f2add(s1[q], wb);
                    sqa[q] = f2fma(wa, a, sqa[q]);
                    sqb[q] = f2fma(wb, b, sqb[q]);
                    srr[q] = f2fma(wa, b, srr[q]);
                }
            }
            ulonglong2 t;
            t.x = s0[0]; t.y = s0[1];
            *reinterpret_cast<ulonglong2*>(&vsbuf[bufA][0][8 + c0]) = t;
            t.x = s1[0]; t.y = s1[1];
            *reinterpret_cast<ulonglong2*>(&vsbuf[bufA][1][8 + c0]) = t;
            t.x = f2add(sqa[0], sqb[0]); t.y = f2add(sqa[1], sqb[1]);
            *reinterpret_cast<ulonglong2*>(&vsbuf[bufA][2][8 + c0]) = t;
            t.x = srr[0]; t.y = srr[1];
            *reinterpret_cast<ulonglong2*>(&vsbuf[bufA][3][8 + c0]) = t;
        }

        // ---------- Row B: vertical conv -> smem + own-col regs ----------
#pragma unroll
        for (int k = 0; k < 10; ++k) {
#pragma unroll
            for (int q = 0; q < 2; ++q) { ra[k][q] = ra[k + 1][q]; rb[k][q] = rb[k + 1][q]; }
        }
#pragma unroll
        for (int q = 0; q < 2; ++q) { ra[10][q] = na[q]; rb[10][q] = nb[q]; }
        load_row_pk(pa, r0 + 7 + i, c0, na);
        load_row_pk(pb, r0 + 7 + i, c0, nb);

        u64 own[4][2];
        {
            u64 s0[2], s1[2], sqa[2], sqb[2], srr[2];
#pragma unroll
            for (int q = 0; q < 2; ++q) {
                u64 a = ra[5][q], b = rb[5][q];
                u64 wa = f2mul(WKP[5], a);
                u64 wb = f2mul(WKP[5], b);
                s0[q] = wa; s1[q] = wb;
                sqa[q] = f2mul(wa, a);
                sqb[q] = f2mul(wb, b);
                srr[q] = f2mul(wa, b);
            }
#pragma unroll
            for (int k = 0; k < 11; ++k) {
                if (k == 5) continue;
                const int wi = (k < 5) ? k : (10 - k);
#pragma unroll
                for (int q = 0; q < 2; ++q) {
                    u64 a = ra[k][q], b = rb[k][q];
                    u64 wa = f2mul(WKP[wi], a);
                    u64 wb = f2mul(WKP[wi], b);
                    s0[q]  = f2add(s0[q], wa);
                    s1[q]  = f2add(s1[q], wb);
                    sqa[q] = f2fma(wa, a, sqa[q]);
                    sqb[q] = f2fma(wb, b, sqb[q]);
                    srr[q] = f2fma(wa, b, srr[q]);
                }
            }
            u64 qq[2] = {f2add(sqa[0], sqb[0]), f2add(sqa[1], sqb[1])};
            ulonglong2 t;
            t.x = s0[0]; t.y = s0[1];
            *reinterpret_cast<ulonglong2*>(&vsbuf[bufB][0][8 + c0]) = t;
            t.x = s1[0]; t.y = s1[1];
            *reinterpret_cast<ulonglong2*>(&vsbuf[bufB][1][8 + c0]) = t;
            t.x = qq[0]; t.y = qq[1];
            *reinterpret_cast<ulonglong2*>(&vsbuf[bufB][2][8 + c0]) = t;
            t.x = srr[0]; t.y = srr[1];
            *reinterpret_cast<ulonglong2*>(&vsbuf[bufB][3][8 + c0]) = t;
            own[0][0] = s0[0]; own[0][1] = s0[1];
            own[1][0] = s1[0]; own[1][1] = s1[1];
            own[2][0] = qq[0]; own[2][1] = qq[1];
            own[3][0] = srr[0]; own[3][1] = srr[1];
        }

        __syncthreads();  // the ONLY barrier per 2 rows

        // ---------- Horizontal + map, row A (all from smem) ----------
        {
            float cv[4][4];
#pragma unroll
            for (int f = 0; f < 4; ++f) {
                float v[20];
#pragma unroll
                for (int q5 = 0; q5 < 5; ++q5) {
                    float4 t = *reinterpret_cast<const float4*>(
                        &vsbuf[bufA][f][c0 + 4 * q5]);
                    v[4 * q5 + 0] = t.x; v[4 * q5 + 1] = t.y;
                    v[4 * q5 + 2] = t.z; v[4 * q5 + 3] = t.w;
                }
#pragma unroll
                for (int j = 0; j < 4; ++j) {
                    float s = KW[5] * v[8 + j];
#pragma unroll
                    for (int k = 0; k < 11; ++k) {
                        if (k == 5) continue;
                        s += KW[k] * v[3 + j + k];
                    }
                    cv[f][j] = s;
                }
            }
#pragma unroll
            for (int q = 0; q < 2; ++q) {
                u64 m1 = pk2(cv[0][2 * q], cv[0][2 * q + 1]);
                u64 m2 = pk2(cv[1][2 * q], cv[1][2 * q + 1]);
                u64 q2 = pk2(cv[2][2 * q], cv[2][2 * q + 1]);
                u64 rr = pk2(cv[3][2 * q], cv[3][2 * q + 1]);
                u64 m12 = f2mul(m1, m2);
                u64 sms = f2fma(m2, m2, f2mul(m1, m1));
                u64 num1 = f2fma(TWO, m12, C1);
                u64 sig12 = f2fma(m12, NEG1, rr);
                u64 num2 = f2fma(TWO, sig12, C2);
                u64 den1 = f2add(sms, C1);
                u64 den2 = f2add(f2fma(sms, NEG1, q2), C2);
                u64 num = f2mul(num1, num2);
                u64 den = f2mul(den1, den2);
                float n0, n1, d0, d1;
                upk2(num, n0, n1);
                upk2(den, d0, d1);
                acc += __fdividef(n0, d0);
                acc += __fdividef(n1, d1);
            }
        }

        // ---------- Horizontal + map, row B (own cols from regs) ----------
        {
            float cv[4][4];
#pragma unroll
            for (int f = 0; f < 4; ++f) {
                float v[20];
                float4 L0 = *reinterpret_cast<const float4*>(&vsbuf[bufB][f][c0]);
                float4 L1 = *reinterpret_cast<const float4*>(&vsbuf[bufB][f][c0 + 4]);
                float4 R0 = *reinterpret_cast<const float4*>(&vsbuf[bufB][f][c0 + 12]);
                float4 R1 = *reinterpret_cast<const float4*>(&vsbuf[bufB][f][c0 + 16]);
                v[0] = L0.x; v[1] = L0.y; v[2] = L0.z; v[3] = L0.w;
                v[4] = L1.x; v[5] = L1.y; v[6] = L1.z; v[7] = L1.w;
                upk2(own[f][0], v[8], v[9]);
                upk2(own[f][1], v[10], v[11]);
                v[12] = R0.x; v[13] = R0.y; v[14] = R0.z; v[15] = R0.w;
                v[16] = R1.x; v[17] = R1.y; v[18] = R1.z; v[19] = R1.w;
#pragma unroll
                for (int j = 0; j < 4; ++j) {
                    float s = KW[5] * v[8 + j];
#pragma unroll
                    for (int k = 0; k < 11; ++k) {
                        if (k == 5) continue;
                        s += KW[k] * v[3 + j + k];
                    }
                    cv[f][j] = s;
                }
            }
#pragma unroll
            for (int q = 0; q < 2; ++q) {
                u64 m1 = pk2(cv[0][2 * q], cv[0][2 * q + 1]);
                u64 m2 = pk2(cv[1][2 * q], cv[1][2 * q + 1]);
                u64 q2 = pk2(cv[2][2 * q], cv[2][2 * q + 1]);
                u64 rr = pk2(cv[3][2 * q], cv[3][2 * q + 1]);
                u64 m12 = f2mul(m1, m2);
                u64 sms = f2fma(m2, m2, f2mul(m1, m1));
                u64 num1 = f2fma(TWO, m12, C1);
                u64 sig12 = f2fma(m12, NEG1, rr);
                u64 num2 = f2fma(TWO, sig12, C2);
                u64 den1 = f2add(sms, C1);
                u64 den2 = f2add(f2fma(sms, NEG1, q2), C2);
                u64 num = f2mul(num1, num2);
                u64 den = f2mul(den1, den2);
                float n0, n1, d0, d1;
                upk2(num, n0, n1);
                upk2(den, d0, d1);
                acc += __fdividef(n0, d0);
                acc += __fdividef(n1, d1);
            }
        }
        // no trailing barrier: next pair writes the other buffer pair,
        // and the pair-after-next is fenced by the next sync.
    }

    // block reduction -> per-block partial
#pragma unroll
    for (int o = 16; o > 0; o >>= 1)
        acc += __shfl_down_sync(0xFFFFFFFFu, acc, o);

    __shared__ float wsum[4];
    __shared__ int is_last;
    if ((tid & 31) == 0) wsum[tid >> 5] = acc;
    __syncthreads();
    if (tid == 0) {
        double s = (double)wsum[0] + (double)wsum[1] + (double)wsum[2] +
                   (double)wsum[3];
        g_partial[blockIdx.y * GX + blockIdx.x] = s;
        __threadfence();
        unsigned old = atomicInc(&g_count, NBLOCKS - 1);  // wraps to 0
        is_last = (old == NBLOCKS - 1);
    }
    __syncthreads();

    // last block finalizes (replay-deterministic: counter wraps to 0)
    if (is_last) {
        __threadfence();
        double s = 0.0;
        for (int i2 = tid; i2 < NBLOCKS; i2 += NTHREADS)
            s += __ldcg(&g_partial[i2]);
#pragma unroll
        for (int o = 16; o > 0; o >>= 1)
            s += __shfl_down_sync(0xFFFFFFFFu, s, o);
        __shared__ double dsm[4];
        if ((tid & 31) == 0) dsm[tid >> 5] = s;
        __syncthreads();
        if (tid == 0) {
            double tot = dsm[0] + dsm[1] + dsm[2] + dsm[3];
            out[0] = (float)(1.0 - tot / NPIX);
        }
    }
}

extern "C" void kernel_launch(void* const* d_in, const int* in_sizes, int n_in,
                              void* d_out, int out_size) {
    const float* sr = (const float*)d_in[0];
    const float* hr = (const float*)d_in[1];
    float* out = (float*)d_out;

    dim3 grid(GX, GY);
    ssim_kernel<<<grid, NTHREADS>>>(sr, hr, out);
}